// round 17
// baseline (speedup 1.0000x reference)
#include <cuda_runtime.h>
#include <math.h>
#include <stdint.h>

#define N_NODES 50000
#define E_EDGES 800000
#define NFEAT   512
#define NHID    128
#define NCLASS  40

// ---------------- scratch (device globals; no allocation) ----------------
__device__ __align__(16) float g_XW1[N_NODES * NHID];   // x @ W1
__device__ __align__(16) float g_XW3[N_NODES * NHID];   // x @ W3
__device__ __align__(16) float g_T1[N_NODES * NHID];    // spmm(adj , xW1)
__device__ __align__(16) float g_T3[N_NODES * NHID];    // spmm(adj2, xW3)
__device__ __align__(16) float g_H1[N_NODES * NCLASS];  // relu(T1+b1) @ W2
__device__ __align__(16) float g_H2[N_NODES * NCLASS];  // relu(T3+b3) @ W4
__device__ __align__(16) float g_O1[N_NODES * NCLASS];  // spmm(adj , H1)
__device__ __align__(16) float g_O2[N_NODES * NCLASS];  // spmm(adj2, H2)

// CSR scratch (per edge list)
__device__ int   g_cnt1[N_NODES],     g_cnt2[N_NODES];
__device__ int   g_rp1[N_NODES + 1],  g_rp2[N_NODES + 1];
__device__ int   g_cur1[N_NODES],     g_cur2[N_NODES];
__device__ int   g_es1[E_EDGES],      g_es2[E_EDGES];
__device__ float g_evv1[E_EDGES],     g_evv2[E_EDGES];

// hierarchical scan scratch
#define SCB 512
#define SNB ((N_NODES + SCB - 1) / SCB)   // 98
__device__ int g_bsum[2][SNB];

// ---------------- CSR build ----------------
__global__ void zero_cnt_kernel() {
    int i = blockIdx.x * blockDim.x + threadIdx.x;
    if (i < N_NODES) { g_cnt1[i] = 0; g_cnt2[i] = 0; }
}

__global__ void hist_kernel(const int* __restrict__ ei1,
                            const int* __restrict__ ei2) {
    int e = blockIdx.x * blockDim.x + threadIdx.x;
    if (e >= E_EDGES) return;
    int* cnt = blockIdx.y ? g_cnt2 : g_cnt1;
    const int* ei = blockIdx.y ? ei2 : ei1;
    atomicAdd(&cnt[ei[E_EDGES + e]], 1);
}

__global__ __launch_bounds__(SCB) void scan_pass1() {
    __shared__ int red[SCB];
    const int list = blockIdx.y;
    const int tid = threadIdx.x;
    int i = blockIdx.x * SCB + tid;
    const int* cnt = list ? g_cnt2 : g_cnt1;
    red[tid] = (i < N_NODES) ? cnt[i] : 0;
    __syncthreads();
#pragma unroll
    for (int off = SCB / 2; off > 0; off >>= 1) {
        if (tid < off) red[tid] += red[tid + off];
        __syncthreads();
    }
    if (tid == 0) g_bsum[list][blockIdx.x] = red[0];
}

__global__ void scan_pass2() {
    __shared__ int s[2][SNB];
    const int tid = threadIdx.x;
    for (int i = tid; i < 2 * SNB; i += blockDim.x)
        s[i / SNB][i % SNB] = g_bsum[i / SNB][i % SNB];
    __syncthreads();
    if (tid < 2) {
        int run = 0;
        for (int i = 0; i < SNB; i++) { int c = s[tid][i]; s[tid][i] = run; run += c; }
    }
    __syncthreads();
    for (int i = tid; i < 2 * SNB; i += blockDim.x)
        g_bsum[i / SNB][i % SNB] = s[i / SNB][i % SNB];
}

__global__ __launch_bounds__(SCB) void scan_pass3() {
    __shared__ int s[SCB];
    const int list = blockIdx.y;
    const int tid = threadIdx.x;
    int i = blockIdx.x * SCB + tid;
    const int* cnt = list ? g_cnt2 : g_cnt1;
    int* rp  = list ? g_rp2  : g_rp1;
    int* cur = list ? g_cur2 : g_cur1;
    int v = (i < N_NODES) ? cnt[i] : 0;
    s[tid] = v;
    __syncthreads();
#pragma unroll
    for (int off = 1; off < SCB; off <<= 1) {
        int add = (tid >= off) ? s[tid - off] : 0;
        __syncthreads();
        s[tid] += add;
        __syncthreads();
    }
    if (i < N_NODES) {
        int ex = g_bsum[list][blockIdx.x] + s[tid] - v;
        rp[i] = ex;
        cur[i] = ex;
    }
    if (i == N_NODES - 1) rp[N_NODES] = E_EDGES;
}

__global__ void scatter_kernel(const int* __restrict__ ei1,
                               const float* __restrict__ ev1,
                               const int* __restrict__ ei2,
                               const float* __restrict__ ev2) {
    int e = blockIdx.x * blockDim.x + threadIdx.x;
    if (e >= E_EDGES) return;
    const int sel = blockIdx.y;
    const int* ei = sel ? ei2 : ei1;
    const float* ev = sel ? ev2 : ev1;
    int* cur = sel ? g_cur2 : g_cur1;
    int* es  = sel ? g_es2  : g_es1;
    float* evs = sel ? g_evv2 : g_evv1;
    int s = ei[e];
    int d = ei[E_EDGES + e];
    int pos = atomicAdd(&cur[d], 1);
    es[pos] = s;
    evs[pos] = ev[e];
}

// ---------------- helpers ----------------
__device__ __forceinline__ float to_tf32(float f) {
    float r;
    asm("cvt.rna.tf32.f32 %0, %1;" : "=f"(r) : "f"(f));
    return r;
}
__device__ __forceinline__ uint32_t cvt_tf32(float f) {
    return __float_as_uint(to_tf32(f));
}
__device__ __forceinline__ void cp_async16(uint32_t dst_smem, const void* src, int src_bytes) {
    asm volatile("cp.async.cg.shared.global [%0], [%1], 16, %2;"
                 :: "r"(dst_smem), "l"(src), "r"(src_bytes));
}
__device__ __forceinline__ void cp_async_commit() {
    asm volatile("cp.async.commit_group;");
}
template<int N>
__device__ __forceinline__ void cp_async_wait() {
    asm volatile("cp.async.wait_group %0;" :: "n"(N));
}

// ---------------- GEMM1 merged (TF32 tensor cores, both towers) ----------
// [XW1 | XW3] = x @ [W1 | W3]  (M=50000, K=512, N=256)
// Block tile 128x256, 8 warps of 64x64, BK=16, 2-stage cp.async pipeline.
// A tile loaded ONCE per block and shared by both towers (halves A traffic).
#define AP  20    // As row pitch (floats)
#define BPW 260   // Bs row pitch (floats) for 256-wide B
#define AS_FLOATS (2 * 128 * AP)                 // 5120
#define GEMM1_SMEM ((AS_FLOATS + 2 * 16 * BPW) * 4)  // 53760 bytes
__global__ __launch_bounds__(256) void gemm1_merged_kernel(
        const float* __restrict__ X,
        const float* __restrict__ W1,
        const float* __restrict__ W3) {
    extern __shared__ float sm[];
    float* Asm = sm;               // [2][128][AP]
    float* Bsm = sm + AS_FLOATS;   // [2][16][BPW]

    const int tid  = threadIdx.x;
    const int lane = tid & 31;
    const int wid  = tid >> 5;           // 0..7
    const int mBase = (wid >> 2) * 64;   // 0 or 64
    const int warpN = wid & 3;           // 0..3
    const int nBase = warpN * 64;        // 0..192
    const int q = lane >> 2;
    const int c = lane & 3;
    const int rowBase = blockIdx.x * 128;

    float acc[4][8][4];
#pragma unroll
    for (int i = 0; i < 4; i++)
#pragma unroll
        for (int j = 0; j < 8; j++)
#pragma unroll
            for (int t = 0; t < 4; t++) acc[i][j][t] = 0.f;

    uint32_t asBase = (uint32_t)__cvta_generic_to_shared(Asm);
    uint32_t bsBase = (uint32_t)__cvta_generic_to_shared(Bsm);

    auto load_tile = [&](int buf, int k0) {
        // A: 128 rows x 16 k = 512 float4 chunks, 2 per thread
#pragma unroll
        for (int i = 0; i < 2; i++) {
            int li = tid + i * 256;          // 0..511
            int r  = li >> 2;                // 0..127
            int cc = (li & 3) << 2;          // 0,4,8,12
            int grow = rowBase + r;
            const float* src = X + (size_t)(grow < N_NODES ? grow : 0) * NFEAT + k0 + cc;
            uint32_t dst = asBase + (uint32_t)((buf * 128 + r) * AP + cc) * 4u;
            cp_async16(dst, src, grow < N_NODES ? 16 : 0);
        }
        // B: 16 k-rows x 256 n = 1024 float4 chunks, 4 per thread
#pragma unroll
        for (int i = 0; i < 4; i++) {
            int li = tid + i * 256;          // 0..1023
            int kr = li >> 6;                // 0..15
            int nc = (li & 63) << 2;         // 0..252
            const float* src = (nc < NHID)
                ? (W1 + (size_t)(k0 + kr) * NHID + nc)
                : (W3 + (size_t)(k0 + kr) * NHID + (nc - NHID));
            uint32_t dst = bsBase + (uint32_t)((buf * 16 + kr) * BPW + nc) * 4u;
            cp_async16(dst, src, 16);
        }
    };

    load_tile(0, 0);
    cp_async_commit();

    const int NK0 = NFEAT / 16;   // 32
    for (int k0i = 0; k0i < NK0; k0i++) {
        const int buf = k0i & 1;

        cp_async_wait<0>();
        __syncthreads();
        if (k0i + 1 < NK0) {
            load_tile(buf ^ 1, (k0i + 1) * 16);
            cp_async_commit();
        }

#pragma unroll
        for (int kk = 0; kk < 16; kk += 8) {
            uint32_t af[4][4];
#pragma unroll
            for (int i = 0; i < 4; i++) {
                int rA = buf * 128 + mBase + i * 16 + q;
                af[i][0] = cvt_tf32(Asm[(rA    ) * AP + kk + c    ]);
                af[i][1] = cvt_tf32(Asm[(rA + 8) * AP + kk + c    ]);
                af[i][2] = cvt_tf32(Asm[(rA    ) * AP + kk + c + 4]);
                af[i][3] = cvt_tf32(Asm[(rA + 8) * AP + kk + c + 4]);
            }
            uint32_t bf[8][2];
#pragma unroll
            for (int j = 0; j < 8; j++) {
                int nC = nBase + j * 8 + q;
                bf[j][0] = cvt_tf32(Bsm[(buf * 16 + kk + c    ) * BPW + nC]);
                bf[j][1] = cvt_tf32(Bsm[(buf * 16 + kk + c + 4) * BPW + nC]);
            }
#pragma unroll
            for (int i = 0; i < 4; i++)
#pragma unroll
                for (int j = 0; j < 8; j++) {
                    asm volatile(
                        "mma.sync.aligned.m16n8k8.row.col.f32.tf32.tf32.f32 "
                        "{%0,%1,%2,%3}, {%4,%5,%6,%7}, {%8,%9}, {%0,%1,%2,%3};"
                        : "+f"(acc[i][j][0]), "+f"(acc[i][j][1]),
                          "+f"(acc[i][j][2]), "+f"(acc[i][j][3])
                        : "r"(af[i][0]), "r"(af[i][1]), "r"(af[i][2]), "r"(af[i][3]),
                          "r"(bf[j][0]), "r"(bf[j][1]));
                }
        }
    }

    // epilogue: warps 0-1 (of each m-row) -> XW1, warps 2-3 -> XW3
    float* Out = (warpN < 2) ? g_XW1 : g_XW3;
    const int colBase = (warpN < 2) ? nBase : nBase - NHID;
#pragma unroll
    for (int i = 0; i < 4; i++) {
        int r0 = rowBase + mBase + i * 16 + q;
        int r1 = r0 + 8;
#pragma unroll
        for (int j = 0; j < 8; j++) {
            int col = colBase + j * 8 + 2 * c;
            if (r0 < N_NODES)
                *reinterpret_cast<float2*>(Out + (size_t)r0 * NHID + col)
                    = make_float2(acc[i][j][0], acc[i][j][1]);
            if (r1 < N_NODES)
                *reinterpret_cast<float2*>(Out + (size_t)r1 * NHID + col)
                    = make_float2(acc[i][j][2], acc[i][j][3]);
        }
    }
}

// ---------------- SPMM F=128 via CSR: warp per dst ----------------
__global__ void spmm128_csr_kernel(int sel) {
    int gw = (blockIdx.x * blockDim.x + threadIdx.x) >> 5;
    if (gw >= N_NODES) return;
    const int lane = threadIdx.x & 31;
    const int* rp = sel ? g_rp2 : g_rp1;
    const int* es = sel ? g_es2 : g_es1;
    const float* evs = sel ? g_evv2 : g_evv1;
    const float4* in = sel ? reinterpret_cast<const float4*>(g_XW3)
                           : reinterpret_cast<const float4*>(g_XW1);
    float4* out = sel ? reinterpret_cast<float4*>(g_T3)
                      : reinterpret_cast<float4*>(g_T1);

    int start = rp[gw];
    int end   = rp[gw + 1];
    float4 acc = make_float4(0.f, 0.f, 0.f, 0.f);

    for (int j = start; j < end; j += 32) {
        int m = end - j;
        int iter = m < 32 ? m : 32;
        int s = 0; float v = 0.f;
        if (lane < iter) { s = es[j + lane]; v = evs[j + lane]; }
        for (int k = 0; k < iter; k++) {
            int   ss = __shfl_sync(0xffffffffu, s, k);
            float vv = __shfl_sync(0xffffffffu, v, k);
            float4 h = in[(size_t)ss * 32 + lane];
            acc.x += vv * h.x; acc.y += vv * h.y;
            acc.z += vv * h.z; acc.w += vv * h.w;
        }
    }
    out[(size_t)gw * 32 + lane] = acc;
}

// ---------------- GEMM2: H = relu(T + b) @ W  (K=128, N=40) ----------------
__global__ void gemm2_kernel(int sel,
                             const float* __restrict__ b1,
                             const float* __restrict__ W2,
                             const float* __restrict__ b3,
                             const float* __restrict__ W4) {
    const float* T = sel ? g_T3 : g_T1;
    const float* b = sel ? b3 : b1;
    const float* W = sel ? W4 : W2;
    float*      Out = sel ? g_H2 : g_H1;

    __shared__ float Ws[NHID][NCLASS];
    __shared__ float bs[NHID];
    __shared__ float Ts[64][17];

    const int tid = threadIdx.x;
    for (int i = tid; i < NHID * NCLASS; i += 256)
        reinterpret_cast<float*>(Ws)[i] = W[i];
    if (tid < NHID) bs[tid] = b[tid];
    __syncthreads();

    const int rowBase = blockIdx.x * 64;
    const int row = tid & 63;
    const int cg = tid >> 6;
    const int col0 = cg * 10;
    const int grow = rowBase + row;

    float acc[10];
#pragma unroll
    for (int j = 0; j < 10; j++) acc[j] = 0.f;

    for (int kb = 0; kb < NHID; kb += 16) {
#pragma unroll
        for (int i = 0; i < 4; i++) {
            int li = tid + i * 256;
            int r = li >> 4;
            int c = li & 15;
            int gr = rowBase + r;
            float v = 0.f;
            if (gr < N_NODES) v = T[(size_t)gr * NHID + kb + c];
            Ts[r][c] = fmaxf(v + bs[kb + c], 0.f);
        }
        __syncthreads();
#pragma unroll
        for (int kk = 0; kk < 16; kk++) {
            float h = Ts[row][kk];
#pragma unroll
            for (int j = 0; j < 10; j++)
                acc[j] += h * Ws[kb + kk][col0 + j];
        }
        __syncthreads();
    }

    if (grow < N_NODES) {
#pragma unroll
        for (int j = 0; j < 10; j++)
            Out[(size_t)grow * NCLASS + col0 + j] = acc[j];
    }
}

// ---------------- SPMM F=40 via CSR: warp per dst (float2 per lane) ------
__global__ void spmm40_csr_kernel(int sel) {
    int gw = (blockIdx.x * blockDim.x + threadIdx.x) >> 5;
    if (gw >= N_NODES) return;
    const int lane = threadIdx.x & 31;
    const int* rp = sel ? g_rp2 : g_rp1;
    const int* es = sel ? g_es2 : g_es1;
    const float* evs = sel ? g_evv2 : g_evv1;
    const float2* in = sel ? reinterpret_cast<const float2*>(g_H2)
                           : reinterpret_cast<const float2*>(g_H1);
    float2* out = sel ? reinterpret_cast<float2*>(g_O2)
                      : reinterpret_cast<float2*>(g_O1);

    int start = rp[gw];
    int end   = rp[gw + 1];
    float2 acc = make_float2(0.f, 0.f);

    for (int j = start; j < end; j += 32) {
        int m = end - j;
        int iter = m < 32 ? m : 32;
        int s = 0; float v = 0.f;
        if (lane < iter) { s = es[j + lane]; v = evs[j + lane]; }
        for (int k = 0; k < iter; k++) {
            int   ss = __shfl_sync(0xffffffffu, s, k);
            float vv = __shfl_sync(0xffffffffu, v, k);
            if (lane < 20) {
                float2 h = in[(size_t)ss * 20 + lane];
                acc.x += vv * h.x;
                acc.y += vv * h.y;
            }
        }
    }
    if (lane < 20) out[(size_t)gw * 20 + lane] = acc;
}

// ---------------- fusion: gate + blend + log_softmax ----------------
__global__ void fuse_kernel(const float* __restrict__ b2,
                            const float* __restrict__ b4,
                            const float* __restrict__ Wl,
                            const float* __restrict__ bl,
                            float* __restrict__ out) {
    __shared__ float Wls[2 * NCLASS][NCLASS];
    __shared__ float b2s[NCLASS], b4s[NCLASS], bls[NCLASS];
    __shared__ float catS[8][2 * NCLASS];

    const int tid = threadIdx.x;
    const int lane = tid & 31;
    const int w = tid >> 5;

    for (int i = tid; i < 2 * NCLASS * NCLASS; i += 256)
        reinterpret_cast<float*>(Wls)[i] = Wl[i];
    if (tid < NCLASS) {
        b2s[tid] = b2[tid];
        b4s[tid] = b4[tid];
        bls[tid] = bl[tid];
    }
    __syncthreads();

    const int n = blockIdx.x * 8 + w;
    if (n >= N_NODES) return;

    for (int i = lane; i < NCLASS; i += 32) {
        catS[w][i]          = g_O1[(size_t)n * NCLASS + i] + b2s[i];
        catS[w][NCLASS + i] = g_O2[(size_t)n * NCLASS + i] + b4s[i];
    }
    __syncwarp();

    float v0, v1 = -1e30f;
    {
        int j = lane;
        float g = bls[j];
#pragma unroll
        for (int i = 0; i < 2 * NCLASS; i++) g += catS[w][i] * Wls[i][j];
        g = 1.f / (1.f + expf(-g));
        v0 = g * catS[w][j] + (1.f - g) * catS[w][NCLASS + j];
    }
    if (lane < 8) {
        int j = 32 + lane;
        float g = bls[j];
#pragma unroll
        for (int i = 0; i < 2 * NCLASS; i++) g += catS[w][i] * Wls[i][j];
        g = 1.f / (1.f + expf(-g));
        v1 = g * catS[w][j] + (1.f - g) * catS[w][NCLASS + j];
    }

    float m = fmaxf(v0, v1);
#pragma unroll
    for (int off = 16; off > 0; off >>= 1)
        m = fmaxf(m, __shfl_xor_sync(0xffffffffu, m, off));
    float s = expf(v0 - m) + (lane < 8 ? expf(v1 - m) : 0.f);
#pragma unroll
    for (int off = 16; off > 0; off >>= 1)
        s += __shfl_xor_sync(0xffffffffu, s, off);
    float ls = m + logf(s);

    out[(size_t)n * NCLASS + lane] = v0 - ls;
    if (lane < 8) out[(size_t)n * NCLASS + 32 + lane] = v1 - ls;
}

// ---------------- launch ----------------
extern "C" void kernel_launch(void* const* d_in, const int* in_sizes, int n_in,
                              void* d_out, int out_size) {
    const float* x   = (const float*)d_in[0];
    const int*   ei1 = (const int*)d_in[1];
    const float* ev1 = (const float*)d_in[2];
    const int*   ei2 = (const int*)d_in[3];
    const float* ev2 = (const float*)d_in[4];
    const float* W1  = (const float*)d_in[5];
    const float* b1  = (const float*)d_in[6];
    const float* W2  = (const float*)d_in[7];
    const float* b2  = (const float*)d_in[8];
    const float* W3  = (const float*)d_in[9];
    const float* b3  = (const float*)d_in[10];
    const float* W4  = (const float*)d_in[11];
    const float* b4  = (const float*)d_in[12];
    const float* Wl  = (const float*)d_in[13];
    const float* bl  = (const float*)d_in[14];
    float* out = (float*)d_out;

    // lazy one-time stream/event setup (host-side only; no device memory)
    static cudaStream_t sGemm = nullptr, sT2 = nullptr;
    static cudaEvent_t evFork = nullptr, evGemm = nullptr,
                       evCsr = nullptr, evT2 = nullptr;
    if (!sGemm) {
        cudaStreamCreateWithFlags(&sGemm, cudaStreamNonBlocking);
        cudaStreamCreateWithFlags(&sT2, cudaStreamNonBlocking);
        cudaEventCreateWithFlags(&evFork, cudaEventDisableTiming);
        cudaEventCreateWithFlags(&evGemm, cudaEventDisableTiming);
        cudaEventCreateWithFlags(&evCsr, cudaEventDisableTiming);
        cudaEventCreateWithFlags(&evT2, cudaEventDisableTiming);
        cudaFuncSetAttribute(gemm1_merged_kernel,
                             cudaFuncAttributeMaxDynamicSharedMemorySize,
                             GEMM1_SMEM);
    }

    const int EB = (E_EDGES + 255) / 256;
    const int SPB = (N_NODES * 32 + 255) / 256;

    // ---- fork: GEMM1 on side stream, CSR build on main stream ----
    cudaEventRecord(evFork, 0);
    cudaStreamWaitEvent(sGemm, evFork, 0);

    gemm1_merged_kernel<<<(N_NODES + 127) / 128, 256, GEMM1_SMEM, sGemm>>>(x, W1, W3);
    cudaEventRecord(evGemm, sGemm);

    zero_cnt_kernel<<<(N_NODES + 255) / 256, 256>>>();
    hist_kernel<<<dim3(EB, 2), 256>>>(ei1, ei2);
    scan_pass1<<<dim3(SNB, 2), SCB>>>();
    scan_pass2<<<1, 256>>>();
    scan_pass3<<<dim3(SNB, 2), SCB>>>();
    scatter_kernel<<<dim3(EB, 2), 256>>>(ei1, ev1, ei2, ev2);

    // join: both CSR + GEMM1 done before spmm
    cudaStreamWaitEvent(0, evGemm, 0);

    // ---- fork towers: tower1 on main, tower2 on sT2 ----
    cudaEventRecord(evCsr, 0);
    cudaStreamWaitEvent(sT2, evCsr, 0);

    // tower 1 (main stream)
    spmm128_csr_kernel<<<SPB, 256>>>(0);
    gemm2_kernel<<<(N_NODES + 63) / 64, 256>>>(0, b1, W2, b3, W4);
    spmm40_csr_kernel<<<SPB, 256>>>(0);

    // tower 2 (side stream)
    spmm128_csr_kernel<<<SPB, 256, 0, sT2>>>(1);
    gemm2_kernel<<<(N_NODES + 63) / 64, 256, 0, sT2>>>(1, b1, W2, b3, W4);
    spmm40_csr_kernel<<<SPB, 256, 0, sT2>>>(1);
    cudaEventRecord(evT2, sT2);

    // join before fuse
    cudaStreamWaitEvent(0, evT2, 0);

    // ---- gated fusion + log_softmax ----
    fuse_kernel<<<(N_NODES + 7) / 8, 256>>>(b2, b4, Wl, bl, out);
}